// round 3
// baseline (speedup 1.0000x reference)
#include <cuda_runtime.h>

// Problem shape (fixed by reference)
#define BB 4
#define HH 16
#define SS 2048
#define DD 64
#define TQ 16          // queries per CTA
#define KC 256         // key chunk staged in smem
#define NTHREADS 512
#define SCALE 0.125f   // 1/sqrt(64)
#define NEGV -1000000000.0f

#define OUT_ELEMS (BB*HH*SS*DD)          // 8388608 floats: attention output
// weights follow at d_out + OUT_ELEMS  : B*H*S*S floats

// smem layout (floats):
//   scores [TQ][SS]          = 32768
//   KsT    [DD][KC] / Vs[KC][DD] = 16384
//   Qs     [TQ][DD] (outbuf in phase 3) = 1024
#define SMEM_FLOATS (TQ*SS + DD*KC + TQ*DD)
#define SMEM_BYTES  (SMEM_FLOATS * 4)

__global__ __launch_bounds__(NTHREADS, 1)
void sdpa_kernel(const float* __restrict__ Q, const float* __restrict__ K,
                 const float* __restrict__ V, const int* __restrict__ mask,
                 float* __restrict__ out, float* __restrict__ wts) {
    extern __shared__ float smem[];
    float* scores = smem;               // TQ * SS
    float* KsT    = smem + TQ*SS;       // DD * KC (phase1) / Vs[KC][DD] (phase3)
    float* Qs     = KsT + DD*KC;        // TQ * DD

    const int h  = blockIdx.x;
    const int q0 = blockIdx.y * TQ;
    const int b  = blockIdx.z;

    const int tid = threadIdx.x;
    const int w   = tid >> 5;
    const int l   = tid & 31;

    const size_t bh = (size_t)(b*HH + h);
    const float* Qb = Q + bh * SS * DD + (size_t)q0 * DD;
    const float* Kb = K + bh * SS * DD;
    const float* Vb = V + bh * SS * DD;
    const int*   Mb = mask + (size_t)b * SS * SS + (size_t)q0 * SS;
    float* Ob = out + bh * SS * DD + (size_t)q0 * DD;
    float* Wb = wts + bh * SS * SS + (size_t)q0 * SS;

    // load Q tile (sync provided by first chunk's post-load barrier)
    for (int i = tid; i < TQ*DD; i += NTHREADS) Qs[i] = Qb[i];

    const int qp = w & 7;     // query pair id: rows 2qp, 2qp+1
    const int kh = w >> 3;    // k-half within chunk: 0 or 1
    const int kposl = kh*128 + 4*l;

    // ================= Phase 1: scores = (Q K^T) * SCALE =================
    for (int kc = 0; kc < SS; kc += KC) {
        __syncthreads();   // protect KsT from previous chunk's readers
        // Stage K chunk transposed: KsT[d][k].
        // warp w owns d0 = 4w; lane l, iter i -> k = 32i + l.
        {
            const int d0 = 4*w;
            #pragma unroll
            for (int i = 0; i < KC/32; i++) {
                const int k = 32*i + l;
                float4 kv = *(const float4*)&Kb[(size_t)(kc + k)*DD + d0];
                KsT[(d0+0)*KC + k] = kv.x;
                KsT[(d0+1)*KC + k] = kv.y;
                KsT[(d0+2)*KC + k] = kv.z;
                KsT[(d0+3)*KC + k] = kv.w;
            }
        }
        __syncthreads();
        // Compute: 2 query rows x 4 consecutive keys per thread.
        float4 a0 = make_float4(0.f,0.f,0.f,0.f);
        float4 a1 = make_float4(0.f,0.f,0.f,0.f);
        const float* q0p = Qs + (2*qp)*DD;
        const float* q1p = Qs + (2*qp+1)*DD;
        const float* kbase = KsT + kposl;
        #pragma unroll
        for (int d = 0; d < DD; d++) {
            float4 kv = *(const float4*)&kbase[d*KC];
            float qa = q0p[d];
            float qb = q1p[d];
            a0.x = fmaf(qa, kv.x, a0.x); a0.y = fmaf(qa, kv.y, a0.y);
            a0.z = fmaf(qa, kv.z, a0.z); a0.w = fmaf(qa, kv.w, a0.w);
            a1.x = fmaf(qb, kv.x, a1.x); a1.y = fmaf(qb, kv.y, a1.y);
            a1.z = fmaf(qb, kv.z, a1.z); a1.w = fmaf(qb, kv.w, a1.w);
        }
        *(float4*)&scores[(2*qp)*SS + kc + kposl] =
            make_float4(a0.x*SCALE, a0.y*SCALE, a0.z*SCALE, a0.w*SCALE);
        *(float4*)&scores[(2*qp+1)*SS + kc + kposl] =
            make_float4(a1.x*SCALE, a1.y*SCALE, a1.z*SCALE, a1.w*SCALE);
    }
    __syncthreads();

    // ================= Phase 2: mask + softmax + write weights ==========
    {
        float4* srow4 = (float4*)(scores + w*SS);
        const int4* mrow4 = (const int4*)(Mb + (size_t)w*SS);
        float maxv = -3.0e38f;
        #pragma unroll 4
        for (int i = l; i < SS/4; i += 32) {
            float4 s = srow4[i];
            int4 m = mrow4[i];
            s.x = (m.x == 0) ? NEGV : s.x;
            s.y = (m.y == 0) ? NEGV : s.y;
            s.z = (m.z == 0) ? NEGV : s.z;
            s.w = (m.w == 0) ? NEGV : s.w;
            srow4[i] = s;
            maxv = fmaxf(maxv, fmaxf(fmaxf(s.x, s.y), fmaxf(s.z, s.w)));
        }
        #pragma unroll
        for (int o = 16; o; o >>= 1)
            maxv = fmaxf(maxv, __shfl_xor_sync(0xffffffffu, maxv, o));

        float sum = 0.f;
        #pragma unroll 4
        for (int i = l; i < SS/4; i += 32) {
            float4 s = srow4[i];
            s.x = __expf(s.x - maxv);
            s.y = __expf(s.y - maxv);
            s.z = __expf(s.z - maxv);
            s.w = __expf(s.w - maxv);
            srow4[i] = s;
            sum += (s.x + s.y) + (s.z + s.w);
        }
        #pragma unroll
        for (int o = 16; o; o >>= 1)
            sum += __shfl_xor_sync(0xffffffffu, sum, o);
        const float inv = 1.0f / sum;

        float4* wrow4 = (float4*)(Wb + (size_t)w * SS);
        #pragma unroll 4
        for (int i = l; i < SS/4; i += 32) {
            float4 s = srow4[i];
            s.x *= inv; s.y *= inv; s.z *= inv; s.w *= inv;
            srow4[i] = s;       // keep normalized p for phase 3
            wrow4[i] = s;       // stream weights to global
        }
    }
    __syncthreads();

    // ================= Phase 3: out = P @ V =============================
    float2 acc0 = make_float2(0.f, 0.f);
    float2 acc1 = make_float2(0.f, 0.f);
    const float* p0row = scores + (2*qp)*SS;
    const float* p1row = scores + (2*qp+1)*SS;
    float* Vs = KsT;   // reuse: natural layout Vs[k][d]
    for (int kc = 0; kc < SS; kc += KC) {
        __syncthreads();
        for (int i = tid*4; i < KC*DD; i += NTHREADS*4) {
            *(float4*)&Vs[i] = *(const float4*)&Vb[(size_t)kc*DD + i];
        }
        __syncthreads();
        const float* pr0 = p0row + kc + kh*128;
        const float* pr1 = p1row + kc + kh*128;
        const float* vsb = Vs + kh*128*DD + 2*l;
        #pragma unroll 8
        for (int k = 0; k < 128; k++) {
            float2 v = *(const float2*)&vsb[k*DD];
            float p0 = pr0[k];
            float p1 = pr1[k];
            acc0.x = fmaf(p0, v.x, acc0.x); acc0.y = fmaf(p0, v.y, acc0.y);
            acc1.x = fmaf(p1, v.x, acc1.x); acc1.y = fmaf(p1, v.y, acc1.y);
        }
    }
    // combine the two k-halves through smem (reuse Qs as outbuf[TQ][DD])
    float* outbuf = Qs;
    __syncthreads();
    if (kh == 0) {
        *(float2*)&outbuf[(2*qp)*DD   + 2*l] = acc0;
        *(float2*)&outbuf[(2*qp+1)*DD + 2*l] = acc1;
    }
    __syncthreads();
    if (kh == 1) {
        float2 b0 = *(const float2*)&outbuf[(2*qp)*DD   + 2*l];
        float2 b1 = *(const float2*)&outbuf[(2*qp+1)*DD + 2*l];
        acc0.x += b0.x; acc0.y += b0.y;
        acc1.x += b1.x; acc1.y += b1.y;
        *(float2*)&Ob[(size_t)(2*qp)*DD   + 2*l] = acc0;
        *(float2*)&Ob[(size_t)(2*qp+1)*DD + 2*l] = acc1;
    }
}

extern "C" void kernel_launch(void* const* d_in, const int* in_sizes, int n_in,
                              void* d_out, int out_size) {
    (void)in_sizes; (void)n_in; (void)out_size;
    const float* Q    = (const float*)d_in[0];
    const float* K    = (const float*)d_in[1];
    const float* V    = (const float*)d_in[2];
    const int*   mask = (const int*)d_in[3];
    float* out = (float*)d_out;
    float* wts = out + OUT_ELEMS;

    static int smem_set = 0;
    if (!smem_set) {
        cudaFuncSetAttribute(sdpa_kernel,
                             cudaFuncAttributeMaxDynamicSharedMemorySize,
                             SMEM_BYTES);
        smem_set = 1;
    }

    dim3 grid(HH, SS/TQ, BB);   // h fastest -> mask tile reused across heads in L2
    sdpa_kernel<<<grid, NTHREADS, SMEM_BYTES>>>(Q, K, V, mask, out, wts);
}

// round 4
// speedup vs baseline: 1.0562x; 1.0562x over previous
#include <cuda_runtime.h>
#include <cstdint>

// Problem shape (fixed by reference)
#define BB 4
#define HH 16
#define SS 2048
#define DD 64
#define TQ 16            // queries per CTA
#define KC 128           // key chunk staged in smem
#define NCHUNK (SS/KC)   // 16
#define NT 256
#define SCALE 0.125f     // 1/sqrt(64)
#define NEGV -1000000000.0f

// smem strides chosen for conflict-free MMA fragment loads
#define SSTR 2052        // scores row stride (2052 % 32 == 4 -> A-frag loads conflict-free)
#define KSTR 136         // KsT row stride  (136 % 32 == 8  -> B-frag loads conflict-free)
#define VSTR 132         // VsT row stride  (132 % 32 == 4  -> B-frag loads conflict-free)
#define KPLANE (DD*KSTR) // 8704 floats per K plane (hi or lo)
#define VPLANE (DD*VSTR) // 8448 floats per V plane

#define OUT_ELEMS (BB*HH*SS*DD)   // attention output; weights follow

// smem: scores[16][2052] + K/V hi+lo planes (max 2*KPLANE) + Qs[16][64]
#define SMEM_FLOATS (TQ*SSTR + 2*KPLANE + TQ*DD)
#define SMEM_BYTES  (SMEM_FLOATS * 4)

__device__ __forceinline__ float tf32r(float x) {
    uint32_t u;
    asm("cvt.rna.tf32.f32 %0, %1;" : "=r"(u) : "f"(x));
    return __uint_as_float(u);
}

// D += A(16x8, tf32) * B(8x8, tf32), fp32 accumulate
#define MMA8(d, a0, a1, a2, a3, b0, b1)                                        \
    asm volatile(                                                              \
        "mma.sync.aligned.m16n8k8.row.col.f32.tf32.tf32.f32 "                  \
        "{%0,%1,%2,%3}, {%4,%5,%6,%7}, {%8,%9}, {%0,%1,%2,%3};"                \
        : "+f"(d[0]), "+f"(d[1]), "+f"(d[2]), "+f"(d[3])                       \
        : "r"(__float_as_uint(a0)), "r"(__float_as_uint(a1)),                  \
          "r"(__float_as_uint(a2)), "r"(__float_as_uint(a3)),                  \
          "r"(__float_as_uint(b0)), "r"(__float_as_uint(b1)))

__global__ __launch_bounds__(NT, 1)
void sdpa_tc(const float* __restrict__ Q, const float* __restrict__ K,
             const float* __restrict__ V, const int* __restrict__ mask,
             float* __restrict__ out, float* __restrict__ wts) {
    extern __shared__ float smem[];
    float* scores = smem;                   // TQ * SSTR
    float* KVbuf  = smem + TQ * SSTR;       // hi plane; lo plane follows
    float* Qs     = KVbuf + 2 * KPLANE;     // TQ * DD

    const int h  = blockIdx.x;
    const int q0 = blockIdx.y * TQ;
    const int b  = blockIdx.z;

    const int tid = threadIdx.x;
    const int w   = tid >> 5;     // warp 0..7
    const int l   = tid & 31;
    const int g   = l >> 2;       // groupID 0..7
    const int tg  = l & 3;        // threadID-in-group 0..3

    const size_t bh = (size_t)(b * HH + h);
    const float4* Q4 = (const float4*)(Q + bh * SS * DD + (size_t)q0 * DD);
    const float4* K4 = (const float4*)(K + bh * SS * DD);
    const float4* V4 = (const float4*)(V + bh * SS * DD);
    const int*    Mb = mask + (size_t)b * SS * SS + (size_t)q0 * SS;
    float* Ob = out + bh * SS * DD + (size_t)q0 * DD;
    float* Wb = wts + bh * SS * SS + (size_t)q0 * SS;

    // Q tile to smem (256 float4 == NT threads)
    ((float4*)Qs)[tid] = Q4[tid];

    // Prefetch K chunk 0 into registers: thread owns d-cols {4w..4w+3, 4w+32..35}, keys 32i+l
    float4 pre[8];
#pragma unroll
    for (int p = 0; p < 2; p++)
#pragma unroll
        for (int i = 0; i < 4; i++)
            pre[p * 4 + i] = K4[(size_t)(32 * i + l) * (DD / 4) + w + 8 * p];

    __syncthreads();

    // Q fragments (hi/lo tf32 split), held in registers for the whole phase 1.
    // a0=[g][8dk+tg] a1=[g+8][8dk+tg] a2=[g][8dk+tg+4] a3=[g+8][8dk+tg+4]
    float qh[8][4], ql[8][4];
#pragma unroll
    for (int dk = 0; dk < 8; dk++) {
        float v0 = Qs[g * DD + 8 * dk + tg];
        float v1 = Qs[(g + 8) * DD + 8 * dk + tg];
        float v2 = Qs[g * DD + 8 * dk + tg + 4];
        float v3 = Qs[(g + 8) * DD + 8 * dk + tg + 4];
        qh[dk][0] = tf32r(v0); ql[dk][0] = tf32r(v0 - qh[dk][0]);
        qh[dk][1] = tf32r(v1); ql[dk][1] = tf32r(v1 - qh[dk][1]);
        qh[dk][2] = tf32r(v2); ql[dk][2] = tf32r(v2 - qh[dk][2]);
        qh[dk][3] = tf32r(v3); ql[dk][3] = tf32r(v3 - qh[dk][3]);
    }

    // ================= Phase 1: scores = (Q K^T) * SCALE (3xTF32 MMA) ======
    {
        float* KH = KVbuf;
        float* KL = KVbuf + KPLANE;
        for (int c = 0; c < NCHUNK; c++) {
            // Stage prefetched K chunk, transposed + hi/lo split.
#pragma unroll
            for (int p = 0; p < 2; p++) {
                const int d0 = 4 * w + 32 * p;
#pragma unroll
                for (int i = 0; i < 4; i++) {
                    const int k = 32 * i + l;
                    float4 v = pre[p * 4 + i];
                    float x, hi;
                    x = v.x; hi = tf32r(x); KH[(d0 + 0) * KSTR + k] = hi; KL[(d0 + 0) * KSTR + k] = tf32r(x - hi);
                    x = v.y; hi = tf32r(x); KH[(d0 + 1) * KSTR + k] = hi; KL[(d0 + 1) * KSTR + k] = tf32r(x - hi);
                    x = v.z; hi = tf32r(x); KH[(d0 + 2) * KSTR + k] = hi; KL[(d0 + 2) * KSTR + k] = tf32r(x - hi);
                    x = v.w; hi = tf32r(x); KH[(d0 + 3) * KSTR + k] = hi; KL[(d0 + 3) * KSTR + k] = tf32r(x - hi);
                }
            }
            __syncthreads();
            // Prefetch next chunk (in flight during the MMAs below)
            if (c + 1 < NCHUNK) {
#pragma unroll
                for (int p = 0; p < 2; p++)
#pragma unroll
                    for (int i = 0; i < 4; i++)
                        pre[p * 4 + i] =
                            K4[(size_t)((c + 1) * KC + 32 * i + l) * (DD / 4) + w + 8 * p];
            }

            // Each warp: 2 n-tiles (16 keys) of this chunk, all 16 query rows.
            float acc[2][4] = {{0.f, 0.f, 0.f, 0.f}, {0.f, 0.f, 0.f, 0.f}};
#pragma unroll
            for (int dk = 0; dk < 8; dk++) {
#pragma unroll
                for (int jn = 0; jn < 2; jn++) {
                    const int nc = (2 * w + jn) * 8;
                    const float* ph = &KH[(8 * dk + tg) * KSTR + nc + g];
                    const float* pl = &KL[(8 * dk + tg) * KSTR + nc + g];
                    float bh0 = ph[0], bh1 = ph[4 * KSTR];
                    float bl0 = pl[0], bl1 = pl[4 * KSTR];
                    MMA8(acc[jn], qh[dk][0], qh[dk][1], qh[dk][2], qh[dk][3], bh0, bh1);
                    MMA8(acc[jn], qh[dk][0], qh[dk][1], qh[dk][2], qh[dk][3], bl0, bl1);
                    MMA8(acc[jn], ql[dk][0], ql[dk][1], ql[dk][2], ql[dk][3], bh0, bh1);
                }
            }
#pragma unroll
            for (int jn = 0; jn < 2; jn++) {
                const int col = c * KC + (2 * w + jn) * 8 + 2 * tg;
                *(float2*)&scores[g * SSTR + col] =
                    make_float2(acc[jn][0] * SCALE, acc[jn][1] * SCALE);
                *(float2*)&scores[(g + 8) * SSTR + col] =
                    make_float2(acc[jn][2] * SCALE, acc[jn][3] * SCALE);
            }
            __syncthreads();
        }
    }

    // Prefetch V chunk 0 now so it overlaps the softmax phase.
#pragma unroll
    for (int p = 0; p < 2; p++)
#pragma unroll
        for (int i = 0; i < 4; i++)
            pre[p * 4 + i] = V4[(size_t)(32 * i + l) * (DD / 4) + w + 8 * p];

    // ================= Phase 2: mask + softmax + write weights =============
#pragma unroll
    for (int rr = 0; rr < 2; rr++) {
        const int r = 2 * w + rr;
        float4* srow4 = (float4*)(scores + r * SSTR);
        const int4* mrow4 = (const int4*)(Mb + (size_t)r * SS);
        float maxv = -3.0e38f;
#pragma unroll 4
        for (int i = l; i < SS / 4; i += 32) {
            float4 s = srow4[i];
            int4 m = mrow4[i];
            s.x = (m.x == 0) ? NEGV : s.x;
            s.y = (m.y == 0) ? NEGV : s.y;
            s.z = (m.z == 0) ? NEGV : s.z;
            s.w = (m.w == 0) ? NEGV : s.w;
            srow4[i] = s;
            maxv = fmaxf(maxv, fmaxf(fmaxf(s.x, s.y), fmaxf(s.z, s.w)));
        }
#pragma unroll
        for (int o = 16; o; o >>= 1)
            maxv = fmaxf(maxv, __shfl_xor_sync(0xffffffffu, maxv, o));

        float sum = 0.f;
#pragma unroll 4
        for (int i = l; i < SS / 4; i += 32) {
            float4 s = srow4[i];
            s.x = __expf(s.x - maxv);
            s.y = __expf(s.y - maxv);
            s.z = __expf(s.z - maxv);
            s.w = __expf(s.w - maxv);
            srow4[i] = s;
            sum += (s.x + s.y) + (s.z + s.w);
        }
#pragma unroll
        for (int o = 16; o; o >>= 1)
            sum += __shfl_xor_sync(0xffffffffu, sum, o);
        const float inv = 1.0f / sum;

        float4* wrow4 = (float4*)(Wb + (size_t)r * SS);
#pragma unroll 4
        for (int i = l; i < SS / 4; i += 32) {
            float4 s = srow4[i];
            s.x *= inv; s.y *= inv; s.z *= inv; s.w *= inv;
            srow4[i] = s;   // normalized P for phase 3
            wrow4[i] = s;   // stream weights to global
        }
    }
    __syncthreads();

    // ================= Phase 3: out = P @ V (3xTF32 MMA) ===================
    {
        float* VH = KVbuf;
        float* VL = KVbuf + VPLANE;
        const int n0 = 8 * w;   // each warp owns 8 d-columns
        float oacc[2][4] = {{0.f, 0.f, 0.f, 0.f}, {0.f, 0.f, 0.f, 0.f}};

        for (int c = 0; c < NCHUNK; c++) {
            // Stage V chunk transposed + split
#pragma unroll
            for (int p = 0; p < 2; p++) {
                const int d0 = 4 * w + 32 * p;
#pragma unroll
                for (int i = 0; i < 4; i++) {
                    const int k = 32 * i + l;
                    float4 v = pre[p * 4 + i];
                    float x, hi;
                    x = v.x; hi = tf32r(x); VH[(d0 + 0) * VSTR + k] = hi; VL[(d0 + 0) * VSTR + k] = tf32r(x - hi);
                    x = v.y; hi = tf32r(x); VH[(d0 + 1) * VSTR + k] = hi; VL[(d0 + 1) * VSTR + k] = tf32r(x - hi);
                    x = v.z; hi = tf32r(x); VH[(d0 + 2) * VSTR + k] = hi; VL[(d0 + 2) * VSTR + k] = tf32r(x - hi);
                    x = v.w; hi = tf32r(x); VH[(d0 + 3) * VSTR + k] = hi; VL[(d0 + 3) * VSTR + k] = tf32r(x - hi);
                }
            }
            __syncthreads();
            if (c + 1 < NCHUNK) {
#pragma unroll
                for (int p = 0; p < 2; p++)
#pragma unroll
                    for (int i = 0; i < 4; i++)
                        pre[p * 4 + i] =
                            V4[(size_t)((c + 1) * KC + 32 * i + l) * (DD / 4) + w + 8 * p];
            }

#pragma unroll
            for (int kt = 0; kt < 16; kt += 2) {
#pragma unroll
                for (int u = 0; u < 2; u++) {
                    const int k0  = (kt + u) * 8;     // key offset within chunk
                    const int kgl = c * KC + k0;      // global key (scores col)
                    // A fragment from normalized P (fp32 in smem), split on the fly
                    float a0 = scores[g * SSTR + kgl + tg];
                    float a1 = scores[(g + 8) * SSTR + kgl + tg];
                    float a2 = scores[g * SSTR + kgl + tg + 4];
                    float a3 = scores[(g + 8) * SSTR + kgl + tg + 4];
                    float h0 = tf32r(a0), h1 = tf32r(a1), h2 = tf32r(a2), h3 = tf32r(a3);
                    float l0 = tf32r(a0 - h0), l1 = tf32r(a1 - h1);
                    float l2 = tf32r(a2 - h2), l3 = tf32r(a3 - h3);
                    const float* ph = &VH[(n0 + g) * VSTR + k0 + tg];
                    const float* pl = &VL[(n0 + g) * VSTR + k0 + tg];
                    float bh0 = ph[0], bh1 = ph[4];
                    float bl0 = pl[0], bl1 = pl[4];
                    MMA8(oacc[u], h0, h1, h2, h3, bh0, bh1);
                    MMA8(oacc[u], h0, h1, h2, h3, bl0, bl1);
                    MMA8(oacc[u], l0, l1, l2, l3, bh0, bh1);
                }
            }
            __syncthreads();
        }

        const int col = n0 + 2 * tg;
        *(float2*)&Ob[(size_t)g * DD + col] =
            make_float2(oacc[0][0] + oacc[1][0], oacc[0][1] + oacc[1][1]);
        *(float2*)&Ob[(size_t)(g + 8) * DD + col] =
            make_float2(oacc[0][2] + oacc[1][2], oacc[0][3] + oacc[1][3]);
    }
}

extern "C" void kernel_launch(void* const* d_in, const int* in_sizes, int n_in,
                              void* d_out, int out_size) {
    (void)in_sizes; (void)n_in; (void)out_size;
    const float* Q    = (const float*)d_in[0];
    const float* K    = (const float*)d_in[1];
    const float* V    = (const float*)d_in[2];
    const int*   mask = (const int*)d_in[3];
    float* out = (float*)d_out;
    float* wts = out + OUT_ELEMS;

    static int smem_set = 0;
    if (!smem_set) {
        cudaFuncSetAttribute(sdpa_tc,
                             cudaFuncAttributeMaxDynamicSharedMemorySize,
                             SMEM_BYTES);
        smem_set = 1;
    }

    dim3 grid(HH, SS / TQ, BB);  // h fastest -> mask tile reused across heads in L2
    sdpa_tc<<<grid, NT, SMEM_BYTES>>>(Q, K, V, mask, out, wts);
}